// round 14
// baseline (speedup 1.0000x reference)
#include <cuda_runtime.h>
#include <math.h>

#define NROWS  4096
#define BSAMP  2048
#define EDIM   256
#define INV_T  14.2857142857142857f   // 1/0.07
#define NTILES 1088                   // upper-triangular tiles: sum_{ic=0}^{15} 8*(16-ic)
#define GRIDP  296                    // 2 blocks/SM * 148 SMs -> single wave

// ---- scratch (device globals: no allocation allowed) ----
__device__ float4       g_Fn4[NROWS * (EDIM / 4)];   // normalized features, 4 MB
__device__ unsigned int g_bits[BSAMP];               // 10-bit label masks
__device__ float        g_part_i[16][NROWS][10];     // i-role partials, slot = j-chunk
__device__ float        g_part_j[128][NROWS][10];    // j-role partials, slot = i-tile (21 MB)
__device__ float        g_rowloss[NROWS];
__device__ int          g_rowfin[NROWS];
__device__ unsigned int g_ctr;                       // work-stealing cursor

// ---------------------------------------------------------------------------
// Kernel 1: per-head L2 normalize. One block per row (256 threads = E dims).
// ---------------------------------------------------------------------------
__global__ void prep_kernel(const float* __restrict__ feat) {
    int row = blockIdx.x;
    int t   = threadIdx.x;                 // 0..255
    int b   = row & (BSAMP - 1);
    int v   = row >> 11;
    float x = feat[((size_t)b * 2 + v) * EDIM + t];
    float sq = x * x;
    #pragma unroll
    for (int o = 16; o > 0; o >>= 1) sq += __shfl_down_sync(0xffffffffu, sq, o);
    __shared__ float wsumS[8];
    if ((t & 31) == 0) wsumS[t >> 5] = sq;
    __syncthreads();
    int h = t >> 6;                        // head = 64-wide chunk -> warps 2h,2h+1
    float ss  = wsumS[2 * h] + wsumS[2 * h + 1];
    float nrm = fmaxf(sqrtf(ss), 1e-12f);
    ((float*)g_Fn4)[(size_t)row * EDIM + t] = x / nrm;
}

// ---------------------------------------------------------------------------
// Kernel 2: pack labels into bitmasks; reset the work-stealing cursor.
// ---------------------------------------------------------------------------
__global__ void bits_kernel(const float* __restrict__ labels) {
    int b = blockIdx.x * blockDim.x + threadIdx.x;
    if (b == 0) g_ctr = GRIDP;             // reset every launch/replay
    if (b < BSAMP) {
        unsigned int bits = 0u;
        #pragma unroll
        for (int d = 0; d < 10; d++)
            if (labels[b * 10 + d] != 0.0f) bits |= (1u << d);
        g_bits[b] = bits;
    }
}

// ---------------------------------------------------------------------------
// Kernel 3: persistent symmetric Gram + softmax-statistics pass (work-stealing).
// Tiles: 32 i-rows x 256 j-cols, only (it, jc) with jc >= it/8 (1088 tiles).
// Each pair (p<q) gated by jg>ig contributes to BOTH rows' statistics:
//   i-role: reduced over lanes -> g_part_i[jc][p]
//   j-role: reduced over io in-regs, over warps via smem -> g_part_j[it][q]
// ---------------------------------------------------------------------------
__global__ void __launch_bounds__(256, 2) pair_kernel() {
    extern __shared__ float4 smem4[];
    float4*       As4 = smem4;                 // 32 rows * 64 f4 (broadcast reads)
    float4*       Bs4 = smem4 + 2048;          // 64 rows * 65 f4 (pad: conflict-free LDS.128)
    unsigned int* jb  = (unsigned int*)(smem4 + 2048 + 4160);  // 64
    float*        red = (float*)Bs4;           // j-role reduce buf, ALIASES Bs (8*64*10 f)
    __shared__ int s_next;                     // stolen tile id

    const int tx  = threadIdx.x;               // 0..31
    const int ty  = threadIdx.y;               // 0..7
    const int tid = ty * 32 + tx;

    int t = blockIdx.x;
    #pragma unroll 1
    while (t < NTILES) {
        // decode linear tile id -> (it, jcs) in the jc >= it/8 triangle
        int ic = 0;
        #pragma unroll 1
        while (ic < 15 && t >= 8 * (16 * (ic + 1) - ((ic + 1) * ic) / 2)) ic++;
        const int rem = t - 8 * (16 * ic - (ic * (ic - 1)) / 2);
        const int wdt = 16 - ic;
        const int it  = 8 * ic + rem / wdt;
        const int jcs = ic + rem % wdt;
        const int ibase = it * 32;

        #pragma unroll
        for (int r = 0; r < 8; r++) {
            int idx = tid + 256 * r;           // 0..2047
            As4[idx] = g_Fn4[ibase * 64 + idx];
        }
        unsigned int ib[4];
        #pragma unroll
        for (int io = 0; io < 4; io++)
            ib[io] = g_bits[(ibase + ty * 4 + io) & (BSAMP - 1)];

        float s[4][4], wsum[4], mcnt[4];
        unsigned int cA[4], cB[4];             // packed 16-bit head counts
        #pragma unroll
        for (int io = 0; io < 4; io++) {
            wsum[io] = 0.f; mcnt[io] = 0.f; cA[io] = 0u; cB[io] = 0u;
            #pragma unroll
            for (int h = 0; h < 4; h++) s[io][h] = 0.f;
        }

        #pragma unroll 1
        for (int jt = 0; jt < 4; jt++) {
            const int jrow0 = jcs * 256 + jt * 64;
            __syncthreads();                   // red reads of prev subtile done / As ready
            #pragma unroll
            for (int r = 0; r < 16; r++) {
                int idx = tid + 256 * r;       // 0..4095
                int row = idx >> 6, c4 = idx & 63;
                Bs4[row * 65 + c4] = g_Fn4[(jrow0 + row) * 64 + c4];
            }
            if (tid < 64) jb[tid] = g_bits[(jrow0 + tid) & (BSAMP - 1)];
            __syncthreads();

            float acc[4][2][4];
            #pragma unroll
            for (int io = 0; io < 4; io++)
                #pragma unroll
                for (int jo = 0; jo < 2; jo++)
                    #pragma unroll
                    for (int h = 0; h < 4; h++) acc[io][jo][h] = 0.f;

            // main FMA loop: per k4 -> 4 broadcast A LDS.128 + 2 B LDS.128 + 32 FMA
            #pragma unroll
            for (int h = 0; h < 4; h++) {
                #pragma unroll 8
                for (int k4 = 0; k4 < 16; k4++) {
                    const int kk = h * 16 + k4;
                    float4 b0 = Bs4[tx * 65 + kk];
                    float4 b1 = Bs4[(tx + 32) * 65 + kk];
                    #pragma unroll
                    for (int io = 0; io < 4; io++) {
                        float4 a = As4[(ty * 4 + io) * 64 + kk];
                        acc[io][0][h] += a.x * b0.x + a.y * b0.y + a.z * b0.z + a.w * b0.w;
                        acc[io][1][h] += a.x * b1.x + a.y * b1.y + a.z * b1.z + a.w * b1.w;
                    }
                }
            }

            // j-role per-subtile accumulators (summed over this thread's 4 io rows)
            float jS[2][4], jw[2], jm[2];
            unsigned int jcA[2], jcB[2];
            #pragma unroll
            for (int jo = 0; jo < 2; jo++) {
                jw[jo] = 0.f; jm[jo] = 0.f; jcA[jo] = 0u; jcB[jo] = 0u;
                #pragma unroll
                for (int h = 0; h < 4; h++) jS[jo][h] = 0.f;
            }

            // epilogue: 8 pairs per thread, dual-role on jg > ig
            #pragma unroll
            for (int io = 0; io < 4; io++) {
                const int ig = ibase + ty * 4 + io;
                #pragma unroll
                for (int jo = 0; jo < 2; jo++) {
                    const int jg = jrow0 + tx + 32 * jo;
                    float d0 = acc[io][jo][0], d1 = acc[io][jo][1];
                    float d2 = acc[io][jo][2], d3 = acc[io][jo][3];
                    bool dual = (jg > ig);
                    float e0 = __expf((d0 - 1.0f) * INV_T);
                    float e1 = __expf((d1 - 1.0f) * INV_T);
                    float e2 = __expf((d2 - 1.0f) * INV_T);
                    float e3 = __expf((d3 - 1.0f) * INV_T);
                    float dm = d0; int hs = 0;   // first-max tie-break == jnp.argmax
                    if (d1 > dm) { dm = d1; hs = 1; }
                    if (d2 > dm) { dm = d2; hs = 2; }
                    if (d3 > dm) { dm = d3; hs = 3; }
                    if (dual) {
                        s[io][0] += e0; s[io][1] += e1; s[io][2] += e2; s[io][3] += e3;
                        jS[jo][0] += e0; jS[jo][1] += e1; jS[jo][2] += e2; jS[jo][3] += e3;
                        if (ib[io] & jb[tx + 32 * jo]) {
                            float dmT = dm * INV_T;
                            unsigned int inc = 1u << ((hs & 1) << 4);
                            wsum[io] += dmT; mcnt[io] += 1.0f;
                            if (hs < 2) cA[io] += inc; else cB[io] += inc;
                            jw[jo] += dmT; jm[jo] += 1.0f;
                            if (hs < 2) jcA[jo] += inc; else jcB[jo] += inc;
                        }
                    }
                }
            }

            // j-role flush: smem stage (aliases Bs) -> reduce over 8 warps -> STG
            __syncthreads();                   // all warps done reading Bs/jb
            #pragma unroll
            for (int jo = 0; jo < 2; jo++) {
                int c = tx + 32 * jo;
                int base = ty * 640 + c * 10;
                red[base + 0] = jS[jo][0]; red[base + 1] = jS[jo][1];
                red[base + 2] = jS[jo][2]; red[base + 3] = jS[jo][3];
                red[base + 4] = jw[jo];    red[base + 5] = jm[jo];
                red[base + 6] = (float)(jcA[jo] & 0xffffu);
                red[base + 7] = (float)(jcA[jo] >> 16);
                red[base + 8] = (float)(jcB[jo] & 0xffffu);
                red[base + 9] = (float)(jcB[jo] >> 16);
            }
            __syncthreads();
            #pragma unroll 1
            for (int o = tid; o < 640; o += 256) {
                float v = 0.f;
                #pragma unroll
                for (int w = 0; w < 8; w++) v += red[w * 640 + o];
                int c = o / 10, st = o % 10;
                g_part_j[it][jrow0 + c][st] = v;
            }
        }

        // steal next tile while doing the i-role reduction
        if (tid == 0) s_next = (int)atomicAdd(&g_ctr, 1u);

        // i-role warp reduction: lanes of a warp share the same 4 i-rows
        #pragma unroll
        for (int o = 16; o > 0; o >>= 1) {
            #pragma unroll
            for (int io = 0; io < 4; io++) {
                #pragma unroll
                for (int h = 0; h < 4; h++)
                    s[io][h] += __shfl_down_sync(0xffffffffu, s[io][h], o);
                wsum[io] += __shfl_down_sync(0xffffffffu, wsum[io], o);
                mcnt[io] += __shfl_down_sync(0xffffffffu, mcnt[io], o);
                cA[io]   += __shfl_down_sync(0xffffffffu, cA[io], o);
                cB[io]   += __shfl_down_sync(0xffffffffu, cB[io], o);
            }
        }
        if (tx == 0) {
            #pragma unroll
            for (int io = 0; io < 4; io++) {
                int ig = ibase + ty * 4 + io;
                float* p = g_part_i[jcs][ig];
                p[0] = s[io][0]; p[1] = s[io][1]; p[2] = s[io][2]; p[3] = s[io][3];
                p[4] = wsum[io]; p[5] = mcnt[io];
                p[6] = (float)(cA[io] & 0xffffu); p[7] = (float)(cA[io] >> 16);
                p[8] = (float)(cB[io] & 0xffffu); p[9] = (float)(cB[io] >> 16);
            }
        }
        __syncthreads();                       // publish s_next; red reads done before As reuse
        t = s_next;
    }
}

// ---------------------------------------------------------------------------
// Kernel 4a: per-row loss, one WARP per row; lanes stride the slot dimension.
//   i-role slots jc = c..15, j-role slots it = 0..8c+7 (c = row/256).
// ---------------------------------------------------------------------------
__global__ void rowloss_kernel() {
    int r    = (blockIdx.x * blockDim.x + threadIdx.x) >> 5;   // 0..4095
    int lane = threadIdx.x & 31;
    int c    = r >> 8;
    float a[10];
    #pragma unroll
    for (int k = 0; k < 10; k++) a[k] = 0.f;
    #pragma unroll 1
    for (int jc = c + lane; jc < 16; jc += 32) {
        const float* p = g_part_i[jc][r];
        #pragma unroll
        for (int k = 0; k < 10; k++) a[k] += p[k];
    }
    #pragma unroll 1
    for (int it = lane; it < 8 * c + 8; it += 32) {
        const float* p = g_part_j[it][r];
        #pragma unroll
        for (int k = 0; k < 10; k++) a[k] += p[k];
    }
    #pragma unroll
    for (int o = 16; o > 0; o >>= 1)
        #pragma unroll
        for (int k = 0; k < 10; k++)
            a[k] += __shfl_down_sync(0xffffffffu, a[k], o);
    if (lane == 0) {
        float loss = 0.f; int fin = 0;
        if (a[5] > 0.0f) {
            float lp = a[4]
                     - a[6] * (INV_T + logf(a[0])) - a[7] * (INV_T + logf(a[1]))
                     - a[8] * (INV_T + logf(a[2])) - a[9] * (INV_T + logf(a[3]));
            loss = -(lp / a[5]);           // temperature/base_temperature == 1
            fin = isfinite(loss) ? 1 : 0;
        }
        g_rowloss[r] = fin ? loss : 0.0f;
        g_rowfin[r]  = fin;
    }
}

// ---------------------------------------------------------------------------
// Kernel 4b: final reduce (one block).
// ---------------------------------------------------------------------------
__global__ void reduce_kernel(float* __restrict__ out) {
    const int t = threadIdx.x;             // 0..255
    double ls = 0.0; int lc = 0;
    #pragma unroll
    for (int r = t; r < NROWS; r += 256) { ls += (double)g_rowloss[r]; lc += g_rowfin[r]; }
    __shared__ double sred[256];
    __shared__ int    cred[256];
    sred[t] = ls; cred[t] = lc;
    __syncthreads();
    for (int o = 128; o > 0; o >>= 1) {
        if (t < o) { sred[t] += sred[t + o]; cred[t] += cred[t + o]; }
        __syncthreads();
    }
    if (t == 0) out[0] = (cred[0] > 0) ? (float)(sred[0] / (double)cred[0]) : 0.0f;
}

// ---------------------------------------------------------------------------
extern "C" void kernel_launch(void* const* d_in, const int* in_sizes, int n_in,
                              void* d_out, int out_size) {
    const float* feat   = (const float*)d_in[0];
    const float* labels = (const float*)d_in[1];
    if (n_in >= 2 && in_sizes[0] == BSAMP * 10) {  // defensive: swap if order differs
        const float* tmp = feat; feat = labels; labels = tmp;
    }
    float* out = (float*)d_out;

    const int smem_bytes = (2048 + 4160) * 16 + 64 * 4;   // 99584 (x2 blocks = 199KB/SM)
    cudaFuncSetAttribute(pair_kernel, cudaFuncAttributeMaxDynamicSharedMemorySize, smem_bytes);

    prep_kernel<<<NROWS, 256>>>(feat);
    bits_kernel<<<8, 256>>>(labels);
    pair_kernel<<<GRIDP, dim3(32, 8), smem_bytes>>>();
    rowloss_kernel<<<512, 256>>>();
    reduce_kernel<<<1, 256>>>(out);
}

// round 16
// speedup vs baseline: 1.6924x; 1.6924x over previous
#include <cuda_runtime.h>
#include <math.h>

#define NROWS  4096
#define BSAMP  2048
#define EDIM   256
#define INV_T  14.2857142857142857f   // 1/0.07
#define NTILES 1088                   // upper-triangular tiles: sum_{ic=0}^{15} 8*(16-ic)
#define GRIDP  296                    // 2 blocks/SM * 148 SMs -> single wave

// ---- scratch (device globals: no allocation allowed) ----
__device__ float4       g_Fn4[NROWS * (EDIM / 4)];   // normalized features, 4 MB
__device__ unsigned int g_bits[BSAMP];               // 10-bit label masks
__device__ float        g_part_i[NROWS][16][10];     // i-role partials, ROW-major slots
__device__ float        g_part_j[NROWS][128][10];    // j-role partials, ROW-major slots (21 MB)
__device__ float        g_rowloss[NROWS];
__device__ int          g_rowfin[NROWS];

// ---------------------------------------------------------------------------
// Kernel 1: per-head L2 normalize. One block per row (256 threads = E dims).
// ---------------------------------------------------------------------------
__global__ void prep_kernel(const float* __restrict__ feat) {
    int row = blockIdx.x;
    int t   = threadIdx.x;                 // 0..255
    int b   = row & (BSAMP - 1);
    int v   = row >> 11;
    float x = feat[((size_t)b * 2 + v) * EDIM + t];
    float sq = x * x;
    #pragma unroll
    for (int o = 16; o > 0; o >>= 1) sq += __shfl_down_sync(0xffffffffu, sq, o);
    __shared__ float wsumS[8];
    if ((t & 31) == 0) wsumS[t >> 5] = sq;
    __syncthreads();
    int h = t >> 6;                        // head = 64-wide chunk -> warps 2h,2h+1
    float ss  = wsumS[2 * h] + wsumS[2 * h + 1];
    float nrm = fmaxf(sqrtf(ss), 1e-12f);
    ((float*)g_Fn4)[(size_t)row * EDIM + t] = x / nrm;
}

// ---------------------------------------------------------------------------
// Kernel 2: pack labels into bitmasks.
// ---------------------------------------------------------------------------
__global__ void bits_kernel(const float* __restrict__ labels) {
    int b = blockIdx.x * blockDim.x + threadIdx.x;
    if (b < BSAMP) {
        unsigned int bits = 0u;
        #pragma unroll
        for (int d = 0; d < 10; d++)
            if (labels[b * 10 + d] != 0.0f) bits |= (1u << d);
        g_bits[b] = bits;
    }
}

// ---------------------------------------------------------------------------
// Kernel 3: persistent symmetric Gram + softmax-statistics pass.
// STATIC grid-stride over tiles (measured-good R3 structure; work-stealing
// reverted after unexplained 2x regression in R14).
// Tiles: 32 i-rows x 256 j-cols, only (it, jc) with jc >= it/8 (1088 tiles).
// Each pair (p<q) gated by jg>ig contributes to BOTH rows' statistics:
//   i-role: reduced over lanes -> g_part_i[p][jc]
//   j-role: reduced over io in-regs, over warps via smem -> g_part_j[q][it]
// ---------------------------------------------------------------------------
__global__ void __launch_bounds__(256, 2) pair_kernel() {
    extern __shared__ float4 smem4[];
    float4*       As4 = smem4;                 // 32 rows * 64 f4 (broadcast reads)
    float4*       Bs4 = smem4 + 2048;          // 64 rows * 65 f4 (pad: conflict-free LDS.128)
    unsigned int* jb  = (unsigned int*)(smem4 + 2048 + 4160);  // 64
    float*        red = (float*)Bs4;           // j-role reduce buf, ALIASES Bs (8*64*10 f)

    const int tx  = threadIdx.x;               // 0..31
    const int ty  = threadIdx.y;               // 0..7
    const int tid = ty * 32 + tx;

    #pragma unroll 1
    for (int t = blockIdx.x; t < NTILES; t += GRIDP) {
        // decode linear tile id -> (it, jcs) in the jc >= it/8 triangle
        int ic = 0;
        #pragma unroll 1
        while (ic < 15 && t >= 8 * (16 * (ic + 1) - ((ic + 1) * ic) / 2)) ic++;
        const int rem = t - 8 * (16 * ic - (ic * (ic - 1)) / 2);
        const int wdt = 16 - ic;
        const int it  = 8 * ic + rem / wdt;
        const int jcs = ic + rem % wdt;
        const int ibase = it * 32;

        __syncthreads();                       // prev tile's red reads done
        #pragma unroll
        for (int r = 0; r < 8; r++) {
            int idx = tid + 256 * r;           // 0..2047
            As4[idx] = g_Fn4[ibase * 64 + idx];
        }
        unsigned int ib[4];
        #pragma unroll
        for (int io = 0; io < 4; io++)
            ib[io] = g_bits[(ibase + ty * 4 + io) & (BSAMP - 1)];

        float s[4][4], wsum[4], mcnt[4];
        unsigned int cA[4], cB[4];             // packed 16-bit head counts
        #pragma unroll
        for (int io = 0; io < 4; io++) {
            wsum[io] = 0.f; mcnt[io] = 0.f; cA[io] = 0u; cB[io] = 0u;
            #pragma unroll
            for (int h = 0; h < 4; h++) s[io][h] = 0.f;
        }

        #pragma unroll 1
        for (int jt = 0; jt < 4; jt++) {
            const int jrow0 = jcs * 256 + jt * 64;
            __syncthreads();                   // red reads of prev subtile done / As ready
            #pragma unroll
            for (int r = 0; r < 16; r++) {
                int idx = tid + 256 * r;       // 0..4095
                int row = idx >> 6, c4 = idx & 63;
                Bs4[row * 65 + c4] = g_Fn4[(jrow0 + row) * 64 + c4];
            }
            if (tid < 64) jb[tid] = g_bits[(jrow0 + tid) & (BSAMP - 1)];
            __syncthreads();

            float acc[4][2][4];
            #pragma unroll
            for (int io = 0; io < 4; io++)
                #pragma unroll
                for (int jo = 0; jo < 2; jo++)
                    #pragma unroll
                    for (int h = 0; h < 4; h++) acc[io][jo][h] = 0.f;

            // main FMA loop: per k4 -> 4 broadcast A LDS.128 + 2 B LDS.128 + 32 FMA
            #pragma unroll
            for (int h = 0; h < 4; h++) {
                #pragma unroll 8
                for (int k4 = 0; k4 < 16; k4++) {
                    const int kk = h * 16 + k4;
                    float4 b0 = Bs4[tx * 65 + kk];
                    float4 b1 = Bs4[(tx + 32) * 65 + kk];
                    #pragma unroll
                    for (int io = 0; io < 4; io++) {
                        float4 a = As4[(ty * 4 + io) * 64 + kk];
                        acc[io][0][h] += a.x * b0.x + a.y * b0.y + a.z * b0.z + a.w * b0.w;
                        acc[io][1][h] += a.x * b1.x + a.y * b1.y + a.z * b1.z + a.w * b1.w;
                    }
                }
            }

            // j-role per-subtile accumulators (summed over this thread's 4 io rows)
            float jS[2][4], jw[2], jm[2];
            unsigned int jcA[2], jcB[2];
            #pragma unroll
            for (int jo = 0; jo < 2; jo++) {
                jw[jo] = 0.f; jm[jo] = 0.f; jcA[jo] = 0u; jcB[jo] = 0u;
                #pragma unroll
                for (int h = 0; h < 4; h++) jS[jo][h] = 0.f;
            }

            // epilogue: 8 pairs per thread, dual-role on jg > ig
            #pragma unroll
            for (int io = 0; io < 4; io++) {
                const int ig = ibase + ty * 4 + io;
                #pragma unroll
                for (int jo = 0; jo < 2; jo++) {
                    const int jg = jrow0 + tx + 32 * jo;
                    float d0 = acc[io][jo][0], d1 = acc[io][jo][1];
                    float d2 = acc[io][jo][2], d3 = acc[io][jo][3];
                    bool dual = (jg > ig);
                    float e0 = __expf((d0 - 1.0f) * INV_T);
                    float e1 = __expf((d1 - 1.0f) * INV_T);
                    float e2 = __expf((d2 - 1.0f) * INV_T);
                    float e3 = __expf((d3 - 1.0f) * INV_T);
                    float dm = d0; int hs = 0;   // first-max tie-break == jnp.argmax
                    if (d1 > dm) { dm = d1; hs = 1; }
                    if (d2 > dm) { dm = d2; hs = 2; }
                    if (d3 > dm) { dm = d3; hs = 3; }
                    if (dual) {
                        s[io][0] += e0; s[io][1] += e1; s[io][2] += e2; s[io][3] += e3;
                        jS[jo][0] += e0; jS[jo][1] += e1; jS[jo][2] += e2; jS[jo][3] += e3;
                        if (ib[io] & jb[tx + 32 * jo]) {
                            float dmT = dm * INV_T;
                            unsigned int inc = 1u << ((hs & 1) << 4);
                            wsum[io] += dmT; mcnt[io] += 1.0f;
                            if (hs < 2) cA[io] += inc; else cB[io] += inc;
                            jw[jo] += dmT; jm[jo] += 1.0f;
                            if (hs < 2) jcA[jo] += inc; else jcB[jo] += inc;
                        }
                    }
                }
            }

            // j-role flush: smem stage (aliases Bs) -> reduce over 8 warps -> STG
            __syncthreads();                   // all warps done reading Bs/jb
            #pragma unroll
            for (int jo = 0; jo < 2; jo++) {
                int c = tx + 32 * jo;
                int base = ty * 640 + c * 10;
                red[base + 0] = jS[jo][0]; red[base + 1] = jS[jo][1];
                red[base + 2] = jS[jo][2]; red[base + 3] = jS[jo][3];
                red[base + 4] = jw[jo];    red[base + 5] = jm[jo];
                red[base + 6] = (float)(jcA[jo] & 0xffffu);
                red[base + 7] = (float)(jcA[jo] >> 16);
                red[base + 8] = (float)(jcB[jo] & 0xffffu);
                red[base + 9] = (float)(jcB[jo] >> 16);
            }
            __syncthreads();
            #pragma unroll 1
            for (int o = tid; o < 640; o += 256) {
                float v = 0.f;
                #pragma unroll
                for (int w = 0; w < 8; w++) v += red[w * 640 + o];
                int c = o / 10, st = o % 10;
                g_part_j[jrow0 + c][it][st] = v;   // row-major slots
            }
        }

        // i-role warp reduction: lanes of a warp share the same 4 i-rows
        #pragma unroll
        for (int o = 16; o > 0; o >>= 1) {
            #pragma unroll
            for (int io = 0; io < 4; io++) {
                #pragma unroll
                for (int h = 0; h < 4; h++)
                    s[io][h] += __shfl_down_sync(0xffffffffu, s[io][h], o);
                wsum[io] += __shfl_down_sync(0xffffffffu, wsum[io], o);
                mcnt[io] += __shfl_down_sync(0xffffffffu, mcnt[io], o);
                cA[io]   += __shfl_down_sync(0xffffffffu, cA[io], o);
                cB[io]   += __shfl_down_sync(0xffffffffu, cB[io], o);
            }
        }
        if (tx == 0) {
            #pragma unroll
            for (int io = 0; io < 4; io++) {
                int ig = ibase + ty * 4 + io;
                float* p = g_part_i[ig][jcs];      // row-major slots
                p[0] = s[io][0]; p[1] = s[io][1]; p[2] = s[io][2]; p[3] = s[io][3];
                p[4] = wsum[io]; p[5] = mcnt[io];
                p[6] = (float)(cA[io] & 0xffffu); p[7] = (float)(cA[io] >> 16);
                p[8] = (float)(cB[io] & 0xffffu); p[9] = (float)(cB[io] >> 16);
            }
        }
    }
}

// ---------------------------------------------------------------------------
// Kernel 4a: per-row loss, one WARP per row; lanes stride the slot dimension.
// Row-major slots: each row's data is one contiguous 5.8 KB block -> coalesced.
//   i-role slots jc = c..15, j-role slots it = 0..8c+7 (c = row/256).
// ---------------------------------------------------------------------------
__global__ void rowloss_kernel() {
    int r    = (blockIdx.x * blockDim.x + threadIdx.x) >> 5;   // 0..4095
    int lane = threadIdx.x & 31;
    int c    = r >> 8;
    float a[10];
    #pragma unroll
    for (int k = 0; k < 10; k++) a[k] = 0.f;
    #pragma unroll 1
    for (int jc = c + lane; jc < 16; jc += 32) {
        const float* p = g_part_i[r][jc];
        #pragma unroll
        for (int k = 0; k < 10; k++) a[k] += p[k];
    }
    #pragma unroll 1
    for (int it = lane; it < 8 * c + 8; it += 32) {
        const float* p = g_part_j[r][it];
        #pragma unroll
        for (int k = 0; k < 10; k++) a[k] += p[k];
    }
    #pragma unroll
    for (int o = 16; o > 0; o >>= 1)
        #pragma unroll
        for (int k = 0; k < 10; k++)
            a[k] += __shfl_down_sync(0xffffffffu, a[k], o);
    if (lane == 0) {
        float loss = 0.f; int fin = 0;
        if (a[5] > 0.0f) {
            float lp = a[4]
                     - a[6] * (INV_T + logf(a[0])) - a[7] * (INV_T + logf(a[1]))
                     - a[8] * (INV_T + logf(a[2])) - a[9] * (INV_T + logf(a[3]));
            loss = -(lp / a[5]);           // temperature/base_temperature == 1
            fin = isfinite(loss) ? 1 : 0;
        }
        g_rowloss[r] = fin ? loss : 0.0f;
        g_rowfin[r]  = fin;
    }
}

// ---------------------------------------------------------------------------
// Kernel 4b: final reduce (one block).
// ---------------------------------------------------------------------------
__global__ void reduce_kernel(float* __restrict__ out) {
    const int t = threadIdx.x;             // 0..255
    double ls = 0.0; int lc = 0;
    #pragma unroll
    for (int r = t; r < NROWS; r += 256) { ls += (double)g_rowloss[r]; lc += g_rowfin[r]; }
    __shared__ double sred[256];
    __shared__ int    cred[256];
    sred[t] = ls; cred[t] = lc;
    __syncthreads();
    for (int o = 128; o > 0; o >>= 1) {
        if (t < o) { sred[t] += sred[t + o]; cred[t] += cred[t + o]; }
        __syncthreads();
    }
    if (t == 0) out[0] = (cred[0] > 0) ? (float)(sred[0] / (double)cred[0]) : 0.0f;
}

// ---------------------------------------------------------------------------
extern "C" void kernel_launch(void* const* d_in, const int* in_sizes, int n_in,
                              void* d_out, int out_size) {
    const float* feat   = (const float*)d_in[0];
    const float* labels = (const float*)d_in[1];
    if (n_in >= 2 && in_sizes[0] == BSAMP * 10) {  // defensive: swap if order differs
        const float* tmp = feat; feat = labels; labels = tmp;
    }
    float* out = (float*)d_out;

    const int smem_bytes = (2048 + 4160) * 16 + 64 * 4;   // 99584 (x2 blocks = 199KB/SM)
    cudaFuncSetAttribute(pair_kernel, cudaFuncAttributeMaxDynamicSharedMemorySize, smem_bytes);

    prep_kernel<<<NROWS, 256>>>(feat);
    bits_kernel<<<8, 256>>>(labels);
    pair_kernel<<<GRIDP, dim3(32, 8), smem_bytes>>>();
    rowloss_kernel<<<512, 256>>>();
    reduce_kernel<<<1, 256>>>(out);
}